// round 5
// baseline (speedup 1.0000x reference)
#include <cuda_runtime.h>
#include <math.h>
#include <stdint.h>

#define Bn   16
#define Tn   2048
#define Dn   512
#define G4n  2048          // 4*D
#define NBLK 128           // persistent blocks (<=148 SMs -> co-resident)
#define PADK 516           // padded row (floats): 516%32==4 -> conflict-free f4

// ---------------- device-global scratch (no runtime allocation) ------------
__device__ float g_xg[(size_t)Bn * Tn * G4n];   // 256 MB: xg for current layer
__device__ float g_y1[(size_t)Bn * Tn * Dn];    // 64 MB: layer-1 output seq
__device__ float g_hbuf[2][Bn * Dn];            // double-buffered h, [b][d]
__device__ unsigned int          g_bar_count;
__device__ volatile unsigned int g_bar_gen;

// ---------------- grid-wide barrier ----------------------------------------
__device__ __forceinline__ void grid_barrier() {
    __syncthreads();
    if (threadIdx.x == 0) {
        unsigned int g = g_bar_gen;
        __threadfence();
        if (atomicAdd(&g_bar_count, 1u) == (unsigned)gridDim.x - 1u) {
            g_bar_count = 0;
            __threadfence();
            g_bar_gen = g + 1;
        } else {
            while (g_bar_gen == g) { }
        }
        __threadfence();
    }
    __syncthreads();
}

__device__ __forceinline__ float sig_f(float x) {
    return 1.0f / (1.0f + expf(-x));
}

// ============================================================================
// SGEMM + bias: C[M=32768, N=2048] = A[M,512] @ W[512,2048] + bias
// 128x128 tile, 256 threads, 8x8 microtile, BK=8.
// ============================================================================
__global__ void __launch_bounds__(256, 2) gemm_bias_kernel(
    const float* __restrict__ A,
    const float* __restrict__ W,
    const float* __restrict__ bias,
    float* __restrict__ C)
{
    const int K = Dn, N = G4n;
    __shared__ __align__(16) float As[8][132];   // transposed [k][m]
    __shared__ __align__(16) float Bs[8][128];   // [k][n]

    const int tid  = threadIdx.x;
    const int bm   = blockIdx.y << 7;
    const int bn   = blockIdx.x << 7;
    const int arow = tid >> 1, acol = (tid & 1) << 2;
    const int brow = tid >> 5, bcol = (tid & 31) << 2;
    const int tr   = (tid >> 4) << 2;
    const int tc   = (tid & 15) << 2;

    float acc[8][8];
#pragma unroll
    for (int i = 0; i < 8; ++i)
#pragma unroll
        for (int j = 0; j < 8; ++j) acc[i][j] = 0.0f;

    for (int k0 = 0; k0 < K; k0 += 8) {
        float4 a = *reinterpret_cast<const float4*>(&A[(size_t)(bm + arow) * K + k0 + acol]);
        float4 b = *reinterpret_cast<const float4*>(&W[(size_t)(k0 + brow) * N + bn + bcol]);
        As[acol + 0][arow] = a.x;
        As[acol + 1][arow] = a.y;
        As[acol + 2][arow] = a.z;
        As[acol + 3][arow] = a.w;
        *reinterpret_cast<float4*>(&Bs[brow][bcol]) = b;
        __syncthreads();

#pragma unroll
        for (int kk = 0; kk < 8; ++kk) {
            float4 a0 = *reinterpret_cast<const float4*>(&As[kk][tr]);
            float4 a1 = *reinterpret_cast<const float4*>(&As[kk][tr + 64]);
            float4 b0 = *reinterpret_cast<const float4*>(&Bs[kk][tc]);
            float4 b1 = *reinterpret_cast<const float4*>(&Bs[kk][tc + 64]);
            float av[8] = {a0.x, a0.y, a0.z, a0.w, a1.x, a1.y, a1.z, a1.w};
            float bv[8] = {b0.x, b0.y, b0.z, b0.w, b1.x, b1.y, b1.z, b1.w};
#pragma unroll
            for (int i = 0; i < 8; ++i)
#pragma unroll
                for (int j = 0; j < 8; ++j)
                    acc[i][j] += av[i] * bv[j];
        }
        __syncthreads();
    }

    float4 bi0 = *reinterpret_cast<const float4*>(&bias[bn + tc]);
    float4 bi1 = *reinterpret_cast<const float4*>(&bias[bn + tc + 64]);
    float bvv[8] = {bi0.x, bi0.y, bi0.z, bi0.w, bi1.x, bi1.y, bi1.z, bi1.w};

#pragma unroll
    for (int i = 0; i < 8; ++i) {
        int r = bm + ((i < 4) ? (tr + i) : (64 + tr + i - 4));
        float4 o0 = make_float4(acc[i][0] + bvv[0], acc[i][1] + bvv[1],
                                acc[i][2] + bvv[2], acc[i][3] + bvv[3]);
        float4 o1 = make_float4(acc[i][4] + bvv[4], acc[i][5] + bvv[5],
                                acc[i][6] + bvv[6], acc[i][7] + bvv[7]);
        *reinterpret_cast<float4*>(&C[(size_t)r * N + bn + tc])      = o0;
        *reinterpret_cast<float4*>(&C[(size_t)r * N + bn + tc + 64]) = o1;
    }
}

// ============================================================================
// Persistent LSTM recurrence for one layer.
// 128 blocks x 128 threads. Block bk owns h-cols d = 4bk+m (m=0..3), i.e.
// 16 gate cols: gcol(c) = (c>>2)*512 + bk*4 + (c&3), c = 0..15.
// Wh slice [c][k] kept in SMEM all layer; c-state in SMEM; h through L2.
// Thread: 2 outputs (b, b+8) for fixed gate col c, each with 4 partial accs.
// ============================================================================
__global__ void __launch_bounds__(128, 1) lstm_recur_kernel(
    const float* __restrict__ Wh,    // [512][2048], this layer
    const float* __restrict__ xg,    // g_xg
    float* __restrict__ yout,        // g_y1 or d_out
    const float* __restrict__ xres)  // nullptr, or x for the residual layer
{
    extern __shared__ float sm[];
    float* W_s  = sm;                 // [16][PADK]  W_s[c][k]
    float* H_s  = sm + 16 * PADK;     // [16][PADK]  H_s[b][k]
    float* gbuf = sm + 32 * PADK;     // [16*16]     gates [b][c]
    float* cbuf = gbuf + 256;         // [64]        c-state [b][m]

    const int tid = threadIdx.x;
    const int bk  = blockIdx.x;

    // ---- prologue: Wh slice -> SMEM, zero c and both h buffers ------------
    for (int idx = tid; idx < 16 * Dn; idx += 128) {
        int c = idx >> 9, k = idx & 511;
        int gcol = ((c >> 2) << 9) + (bk << 2) + (c & 3);
        W_s[c * PADK + k] = Wh[(size_t)k * G4n + gcol];
    }
    if (tid < 64) {
        cbuf[tid] = 0.0f;
        int m = tid & 3, b = tid >> 2;
        int d = (bk << 2) + m;
        g_hbuf[0][b * Dn + d] = 0.0f;
        g_hbuf[1][b * Dn + d] = 0.0f;
        __threadfence();
    }
    grid_barrier();

    const int b1 = tid >> 4;          // 0..7
    const int b2 = b1 + 8;
    const int c  = tid & 15;
    const int gc = ((c >> 2) << 9) + (bk << 2) + (c & 3);
    const float4* Wp = reinterpret_cast<const float4*>(W_s + c * PADK);
    // gate-phase ids
    const int gm = tid & 3, gb = tid >> 2;
    const int gd = (bk << 2) + gm;

    for (int t = 0; t < Tn; ++t) {
        // 1. h(t-1): global double buffer -> SMEM (L2 path, L1 is stale)
        const float4* hb = reinterpret_cast<const float4*>(g_hbuf[(t + 1) & 1]);
#pragma unroll
        for (int j = 0; j < 16; ++j) {
            int idx = j * 128 + tid;           // 0..2047 float4
            int b   = idx >> 7, k4 = idx & 127;
            float4 v = __ldcg(hb + idx);
            *reinterpret_cast<float4*>(H_s + b * PADK + (k4 << 2)) = v;
        }
        // 2. prefetch xg for this thread's two outputs
        float xv1 = __ldg(&xg[((size_t)b1 * Tn + t) * G4n + gc]);
        float xv2 = __ldg(&xg[((size_t)b2 * Tn + t) * G4n + gc]);
        float xrv = 0.0f;
        if (xres != nullptr && tid < 64)
            xrv = __ldg(&xres[((size_t)gb * Tn + t) * Dn + gd]);

        __syncthreads();   // H_s ready

        // 3. two dot products over k=512, 4-way split accumulators
        const float4* H1 = reinterpret_cast<const float4*>(H_s + b1 * PADK);
        const float4* H2 = reinterpret_cast<const float4*>(H_s + b2 * PADK);
        float a0 = 0, a1 = 0, a2 = 0, a3 = 0;
        float e0 = 0, e1 = 0, e2 = 0, e3 = 0;
#pragma unroll 8
        for (int k4 = 0; k4 < 128; ++k4) {
            float4 w  = Wp[k4];
            float4 h1 = H1[k4];
            float4 h2 = H2[k4];
            a0 += w.x * h1.x; a1 += w.y * h1.y;
            a2 += w.z * h1.z; a3 += w.w * h1.w;
            e0 += w.x * h2.x; e1 += w.y * h2.y;
            e2 += w.z * h2.z; e3 += w.w * h2.w;
        }
        gbuf[b1 * 16 + c] = xv1 + (a0 + a1) + (a2 + a3);
        gbuf[b2 * 16 + c] = xv2 + (e0 + e1) + (e2 + e3);
        __syncthreads();

        // 4. gates -> (c,h); write h to global double buffer + output seq
        if (tid < 64) {
            float gi = gbuf[gb * 16 + 0  + gm];
            float gf = gbuf[gb * 16 + 4  + gm];
            float gg = gbuf[gb * 16 + 8  + gm];
            float go = gbuf[gb * 16 + 12 + gm];
            float cn = sig_f(gf) * cbuf[tid] + sig_f(gi) * tanhf(gg);
            float h  = sig_f(go) * tanhf(cn);
            cbuf[tid] = cn;
            __stcg(&g_hbuf[t & 1][gb * Dn + gd], h);
            size_t yi = ((size_t)gb * Tn + t) * Dn + gd;
            yout[yi] = (xres != nullptr) ? (h + xrv) : h;
            __threadfence();
        }
        grid_barrier();
    }
}

// ============================================================================
extern "C" void kernel_launch(void* const* d_in, const int* in_sizes, int n_in,
                              void* d_out, int out_size) {
    const float* x  = (const float*)d_in[0];   // [16,2048,512]
    const float* Wx = (const float*)d_in[1];   // [2,512,2048]
    const float* Wh = (const float*)d_in[2];   // [2,512,2048]
    const float* bb = (const float*)d_in[3];   // [2,2048]
    float* out = (float*)d_out;                // [16,2048,512]

    float *xg_p, *y1_p;
    cudaGetSymbolAddress((void**)&xg_p, g_xg);
    cudaGetSymbolAddress((void**)&y1_p, g_y1);

    const int smem = (32 * PADK + 256 + 64) * (int)sizeof(float);  // ~67.3 KB
    cudaFuncSetAttribute(lstm_recur_kernel,
                         cudaFuncAttributeMaxDynamicSharedMemorySize, smem);

    dim3 ggrid(G4n / 128, (Bn * Tn) / 128);    // 16 x 256

    // ----- layer 0 -----
    gemm_bias_kernel<<<ggrid, 256>>>(x, Wx, bb, xg_p);
    lstm_recur_kernel<<<NBLK, 128, smem>>>(Wh, xg_p, y1_p, nullptr);

    // ----- layer 1 (+ residual) -----
    gemm_bias_kernel<<<ggrid, 256>>>(y1_p, Wx + (size_t)Dn * G4n, bb + G4n, xg_p);
    lstm_recur_kernel<<<NBLK, 128, smem>>>(Wh + (size_t)Dn * G4n, xg_p, out, x);
}

// round 10
// speedup vs baseline: 1.0562x; 1.0562x over previous
#include <cuda_runtime.h>
#include <math.h>
#include <stdint.h>

#define Bn   16
#define Tn   2048
#define Dn   512
#define G4n  2048          // 4*D
#define NBLK 128           // persistent blocks (<=148 SMs -> co-resident)
#define PADK 516           // padded row stride in floats (516%32==4, 16B-aligned)

// ---------------- device-global scratch (no runtime allocation) ------------
__device__ float g_xg[(size_t)Bn * Tn * G4n];   // 256 MB: xg for current layer
__device__ float g_y1[(size_t)Bn * Tn * Dn];    // 64 MB: layer-1 output seq
__device__ float g_hbuf[2][Bn * Dn];            // double-buffered h, [b][d]
__device__ unsigned int          g_bar_count;
__device__ volatile unsigned int g_bar_gen;

// ---------------- grid-wide barrier ----------------------------------------
__device__ __forceinline__ void grid_barrier() {
    __syncthreads();
    if (threadIdx.x == 0) {
        unsigned int g = g_bar_gen;
        __threadfence();
        if (atomicAdd(&g_bar_count, 1u) == (unsigned)gridDim.x - 1u) {
            g_bar_count = 0;
            __threadfence();
            g_bar_gen = g + 1;
        } else {
            while (g_bar_gen == g) { }
        }
        __threadfence();
    }
    __syncthreads();
}

__device__ __forceinline__ float sig_f(float x) {
    return 1.0f / (1.0f + expf(-x));
}

// packed fp32x2 FMA (sm_103a FFMA2; PTX-only form)
__device__ __forceinline__ void ffma2(unsigned long long& d,
                                      unsigned long long a,
                                      unsigned long long b) {
    asm("fma.rn.f32x2 %0, %1, %2, %0;" : "+l"(d) : "l"(a), "l"(b));
}
__device__ __forceinline__ float fsum2(unsigned long long v) {
    float lo, hi;
    asm("mov.b64 {%0, %1}, %2;" : "=f"(lo), "=f"(hi) : "l"(v));
    return lo + hi;
}

// ============================================================================
// SGEMM + bias: C[M=32768, N=2048] = A[M,512] @ W[512,2048] + bias
// 128x128 tile, 256 threads, 8x8 microtile, BK=8, register double buffering.
// ============================================================================
__global__ void __launch_bounds__(256, 2) gemm_bias_kernel(
    const float* __restrict__ A,
    const float* __restrict__ W,
    const float* __restrict__ bias,
    float* __restrict__ C)
{
    const int K = Dn, N = G4n;
    __shared__ __align__(16) float As[8][132];   // transposed [k][m]
    __shared__ __align__(16) float Bs[8][128];   // [k][n]

    const int tid  = threadIdx.x;
    const int bm   = blockIdx.y << 7;
    const int bn   = blockIdx.x << 7;
    const int arow = tid >> 1, acol = (tid & 1) << 2;
    const int brow = tid >> 5, bcol = (tid & 31) << 2;
    const int tr   = (tid >> 4) << 2;
    const int tc   = (tid & 15) << 2;

    float acc[8][8];
#pragma unroll
    for (int i = 0; i < 8; ++i)
#pragma unroll
        for (int j = 0; j < 8; ++j) acc[i][j] = 0.0f;

    float4 areg = *reinterpret_cast<const float4*>(&A[(size_t)(bm + arow) * K + acol]);
    float4 breg = *reinterpret_cast<const float4*>(&W[(size_t)brow * N + bn + bcol]);

#pragma unroll 1
    for (int k0 = 0; k0 < K; k0 += 8) {
        As[acol + 0][arow] = areg.x;
        As[acol + 1][arow] = areg.y;
        As[acol + 2][arow] = areg.z;
        As[acol + 3][arow] = areg.w;
        *reinterpret_cast<float4*>(&Bs[brow][bcol]) = breg;
        __syncthreads();

        if (k0 + 8 < K) {
            areg = *reinterpret_cast<const float4*>(&A[(size_t)(bm + arow) * K + (k0 + 8) + acol]);
            breg = *reinterpret_cast<const float4*>(&W[(size_t)(k0 + 8 + brow) * N + bn + bcol]);
        }

#pragma unroll
        for (int kk = 0; kk < 8; ++kk) {
            float4 a0 = *reinterpret_cast<const float4*>(&As[kk][tr]);
            float4 a1 = *reinterpret_cast<const float4*>(&As[kk][tr + 64]);
            float4 b0 = *reinterpret_cast<const float4*>(&Bs[kk][tc]);
            float4 b1 = *reinterpret_cast<const float4*>(&Bs[kk][tc + 64]);
            float av[8] = {a0.x, a0.y, a0.z, a0.w, a1.x, a1.y, a1.z, a1.w};
            float bv[8] = {b0.x, b0.y, b0.z, b0.w, b1.x, b1.y, b1.z, b1.w};
#pragma unroll
            for (int i = 0; i < 8; ++i)
#pragma unroll
                for (int j = 0; j < 8; ++j)
                    acc[i][j] += av[i] * bv[j];
        }
        __syncthreads();
    }

    float4 bi0 = *reinterpret_cast<const float4*>(&bias[bn + tc]);
    float4 bi1 = *reinterpret_cast<const float4*>(&bias[bn + tc + 64]);
    float bvv[8] = {bi0.x, bi0.y, bi0.z, bi0.w, bi1.x, bi1.y, bi1.z, bi1.w};

#pragma unroll
    for (int i = 0; i < 8; ++i) {
        int r = bm + ((i < 4) ? (tr + i) : (64 + tr + i - 4));
        float4 o0 = make_float4(acc[i][0] + bvv[0], acc[i][1] + bvv[1],
                                acc[i][2] + bvv[2], acc[i][3] + bvv[3]);
        float4 o1 = make_float4(acc[i][4] + bvv[4], acc[i][5] + bvv[5],
                                acc[i][6] + bvv[6], acc[i][7] + bvv[7]);
        *reinterpret_cast<float4*>(&C[(size_t)r * N + bn + tc])      = o0;
        *reinterpret_cast<float4*>(&C[(size_t)r * N + bn + tc + 64]) = o1;
    }
}

// ============================================================================
// Persistent LSTM recurrence, one layer. 128 blocks x 256 threads.
// Block bk owns h-cols d = 4bk+m (m=0..3) => 16 gate cols:
//   gcol(c) = (c>>2)*512 + bk*4 + (c&3),  c = 0..15.
// Wh slice [c][k] SMEM-resident all layer; c-state in SMEM; h via L2.
//
// Compute layout (per thread): outputs (b1,c) and (b1+8,c), HALF of k.
//   lane  = clo(8) x b1q(4):  clo = lane&7, b1q = lane>>3
//   warp  = kh(2) x chi(2) x b1h(2)
//   c = clo + 8*chi,  b1 = b1q + 4*b1h,  k-half = kh
// -> per warp-iter SMEM: W 8 distinct f4 (128B), H 8 distinct f4 (128B).
// Inner loop uses fp32x2 packed FMA over (k, k+1) pairs.
// ============================================================================
__global__ void __launch_bounds__(256, 1) lstm_recur_kernel(
    const float* __restrict__ Wh,    // [512][2048], this layer
    const float* __restrict__ xg,    // g_xg
    float* __restrict__ yout,        // g_y1 or d_out
    const float* __restrict__ xres)  // nullptr, or x (residual, last layer)
{
    extern __shared__ float sm[];
    float* W_s  = sm;                 // [16][PADK]  W_s[c][k]
    float* H_s  = sm + 16 * PADK;     // [16][PADK]  H_s[b][k]
    float* psum = sm + 32 * PADK;     // [2][16][16] partials per k-half
    float* gbuf = psum + 512;         // [16][16]    gates [b][c]
    float* cbuf = gbuf + 256;         // [64]        c-state [b][m]

    const int tid = threadIdx.x;
    const int bk  = blockIdx.x;

    // ---- prologue: Wh slice -> SMEM, zero c and both h buffers ------------
    for (int idx = tid; idx < 16 * Dn; idx += 256) {
        int c = idx >> 9, k = idx & 511;
        int gcol = ((c >> 2) << 9) + (bk << 2) + (c & 3);
        W_s[c * PADK + k] = Wh[(size_t)k * G4n + gcol];
    }
    if (tid < 64) {
        cbuf[tid] = 0.0f;
        int m = tid & 3, b = tid >> 2;
        int d = (bk << 2) + m;
        g_hbuf[0][b * Dn + d] = 0.0f;
        g_hbuf[1][b * Dn + d] = 0.0f;
        __threadfence();
    }
    grid_barrier();

    // compute-phase ids
    const int lane = tid & 31, warp = tid >> 5;
    const int clo = lane & 7,  b1q = lane >> 3;
    const int kh  = warp >> 2, chi = (warp >> 1) & 1, b1h = warp & 1;
    const int cc  = clo + (chi << 3);          // 0..15
    const int b1  = b1q + (b1h << 2);          // 0..7
    const int b2  = b1 + 8;
    const unsigned long long* Wp =
        reinterpret_cast<const unsigned long long*>(W_s + cc * PADK + kh * 256);
    const unsigned long long* H1p =
        reinterpret_cast<const unsigned long long*>(H_s + b1 * PADK + kh * 256);
    const unsigned long long* H2p =
        reinterpret_cast<const unsigned long long*>(H_s + b2 * PADK + kh * 256);

    // finishing-phase ids (one output per thread)
    const int fb = tid >> 4, fc = tid & 15;
    const int fgc = ((fc >> 2) << 9) + (bk << 2) + (fc & 3);
    // gate-phase ids
    const int gm = tid & 3, gb = tid >> 2;
    const int gd = (bk << 2) + gm;

    for (int t = 0; t < Tn; ++t) {
        // 1. h(t-1): global double buffer -> SMEM ([b][k], row pad PADK)
        const float4* hb = reinterpret_cast<const float4*>(g_hbuf[(t + 1) & 1]);
#pragma unroll
        for (int j = 0; j < 8; ++j) {
            int idx = j * 256 + tid;           // 0..2047 float4
            int b   = idx >> 7, k4 = idx & 127;
            float4 v = __ldcg(hb + idx);
            *reinterpret_cast<float4*>(H_s + b * PADK + (k4 << 2)) = v;
        }
        // 2. prefetch xg (finishing layout) + residual (gate layout)
        float xv = __ldg(&xg[((size_t)fb * Tn + t) * G4n + fgc]);
        float xrv = 0.0f;
        if (xres != nullptr && tid < 64)
            xrv = __ldg(&xres[((size_t)gb * Tn + t) * Dn + gd]);

        __syncthreads();   // H_s ready

        // 3. half-k dot products, fp32x2 packed over (k,k+1)
        unsigned long long a0 = 0ull, a1 = 0ull, e0 = 0ull, e1 = 0ull;
#pragma unroll 8
        for (int i = 0; i < 64; ++i) {          // 64 x 16B = 256 floats
            unsigned long long wx = Wp[2 * i],  wy = Wp[2 * i + 1];
            unsigned long long hx = H1p[2 * i], hy = H1p[2 * i + 1];
            unsigned long long gx = H2p[2 * i], gy = H2p[2 * i + 1];
            ffma2(a0, wx, hx); ffma2(a1, wy, hy);
            ffma2(e0, wx, gx); ffma2(e1, wy, gy);
        }
        psum[(kh << 8) + b1 * 16 + cc] = fsum2(a0) + fsum2(a1);
        psum[(kh << 8) + b2 * 16 + cc] = fsum2(e0) + fsum2(e1);
        __syncthreads();

        // 4. combine k-halves + xg -> gates buffer
        gbuf[tid] = xv + psum[tid] + psum[256 + tid];
        __syncthreads();

        // 5. gates -> (c,h); write h to global double buffer + output seq
        if (tid < 64) {
            float gi = gbuf[gb * 16 + 0  + gm];
            float gf = gbuf[gb * 16 + 4  + gm];
            float gg = gbuf[gb * 16 + 8  + gm];
            float go = gbuf[gb * 16 + 12 + gm];
            float cn = sig_f(gf) * cbuf[tid] + sig_f(gi) * tanhf(gg);
            float h  = sig_f(go) * tanhf(cn);
            cbuf[tid] = cn;
            __stcg(&g_hbuf[t & 1][gb * Dn + gd], h);
            size_t yi = ((size_t)gb * Tn + t) * Dn + gd;
            yout[yi] = (xres != nullptr) ? (h + xrv) : h;
            __threadfence();
        }
        grid_barrier();
    }
}

// ============================================================================
extern "C" void kernel_launch(void* const* d_in, const int* in_sizes, int n_in,
                              void* d_out, int out_size) {
    const float* x  = (const float*)d_in[0];   // [16,2048,512]
    const float* Wx = (const float*)d_in[1];   // [2,512,2048]
    const float* Wh = (const float*)d_in[2];   // [2,512,2048]
    const float* bb = (const float*)d_in[3];   // [2,2048]
    float* out = (float*)d_out;                // [16,2048,512]

    float *xg_p, *y1_p;
    cudaGetSymbolAddress((void**)&xg_p, g_xg);
    cudaGetSymbolAddress((void**)&y1_p, g_y1);

    const int smem = (32 * PADK + 512 + 256 + 64) * (int)sizeof(float); // ~69.3 KB
    cudaFuncSetAttribute(lstm_recur_kernel,
                         cudaFuncAttributeMaxDynamicSharedMemorySize, smem);

    dim3 ggrid(G4n / 128, (Bn * Tn) / 128);    // 16 x 256

    // ----- layer 0 -----
    gemm_bias_kernel<<<ggrid, 256>>>(x, Wx, bb, xg_p);
    lstm_recur_kernel<<<NBLK, 256, smem>>>(Wh, xg_p, y1_p, nullptr);

    // ----- layer 1 (+ residual) -----
    gemm_bias_kernel<<<ggrid, 256>>>(y1_p, Wx + (size_t)Dn * G4n, bb + G4n, xg_p);
    lstm_recur_kernel<<<NBLK, 256, smem>>>(Wh + (size_t)Dn * G4n, xg_p, out, x);
}